// round 12
// baseline (speedup 1.0000x reference)
#include <cuda_runtime.h>
#include <cuda_fp16.h>
#include <math.h>

#define H    128
#define SEQ  128
#define BTOT 2048
#define NB   8             // batches per block
#define NBLK (BTOT/NB)     // 256 blocks
#define NTHR 512
#define O5   640           // 512 (W_hh cols) + 128 (W_pq cols), transposed layout

typedef unsigned long long ull;
typedef unsigned int uint32;

// ---------------- device-global scratch -------------------------------------
__device__ float  d_Wt[H*O5];
__device__ float4 d_A4[H];
__device__ float  d_cbias[H];
__device__ float  d_aW[H];
__device__ float  d_G2[512*2];
__device__ float  d_gb[512];
// t-invariant attention pre-activation, f16x2 s-pairs: [b][hh][s/2] -> 64 MiB (L2-resident)
__device__ uint32 d_base2[(size_t)BTOT*H*(SEQ/2)];

// ---------------- f32x2 packed helpers --------------------------------------
__device__ __forceinline__ ull pack2(float x, float y) {
    ull r; asm("mov.b64 %0, {%1,%2};" : "=l"(r) : "f"(x), "f"(y)); return r;
}
__device__ __forceinline__ ull fma2(ull a, ull b, ull c) {
    ull d; asm("fma.rn.f32x2 %0, %1, %2, %3;" : "=l"(d) : "l"(a), "l"(b), "l"(c)); return d;
}
__device__ __forceinline__ void unpack2(ull p, float& x, float& y) {
    asm("mov.b64 {%0,%1}, %2;" : "=f"(x), "=f"(y) : "l"(p));
}
// f16x2 helpers
__device__ __forceinline__ uint32 hadd2u(uint32 a, uint32 b) {
    uint32 r; asm("add.rn.f16x2 %0, %1, %2;" : "=r"(r) : "r"(a), "r"(b)); return r;
}
__device__ __forceinline__ uint32 tanh2u(uint32 x) {
    uint32 r; asm("tanh.approx.f16x2 %0, %1;" : "=r"(r) : "r"(x)); return r;
}

// ---------------- exact transcendentals (R4-bitwise) ------------------------
__device__ __forceinline__ float exp_acc(float y) {
    const float L2E_HI = 1.44269502162933349609375f;
    const float L2E_LO = 1.9259629911266175e-8f;
    float p  = y * L2E_HI;
    float e  = fmaf(y, L2E_HI, -p);
    float pc = fminf(fmaxf(p, -126.0f), 126.0f);
    float nf = rintf(pc);
    int   ni = (int)nf;
    float f  = (pc - nf) + fmaf(y, L2E_LO, e);
    float r  = 1.5252733e-5f;
    r = fmaf(r, f, 1.5403530e-4f);
    r = fmaf(r, f, 1.3333558e-3f);
    r = fmaf(r, f, 9.6181291e-3f);
    r = fmaf(r, f, 5.5504109e-2f);
    r = fmaf(r, f, 2.4022651e-1f);
    r = fmaf(r, f, 6.9314718e-1f);
    r = fmaf(r, f, 1.0f);
    float sc = __int_as_float((ni + 127) << 23);
    return r * sc;
}
__device__ __forceinline__ float rcp_nr(float d) {
    float r;
    asm("rcp.approx.f32 %0, %1;" : "=f"(r) : "f"(d));
    return r * fmaf(-d, r, 2.0f);
}
__device__ __forceinline__ float tanh_acc(float x) {
    float E = exp_acc(x + x);
    float q = rcp_nr(E + 1.0f);
    return 1.0f - (q + q);
}
__device__ __forceinline__ float sig_acc(float x) {
    return rcp_nr(1.0f + exp_acc(-x));
}

// ---------------- phase 0: fold affine algebra (fp64) — UNCHANGED from R4 ---
__global__ void precompute_kernel(
    const float* __restrict__ W_s,  const float* __restrict__ b_s,
    const float* __restrict__ W_ld, const float* __restrict__ b_ld,
    const float* __restrict__ W_d,  const float* __restrict__ b_d,
    const float* __restrict__ W_ih, const float* __restrict__ b_ih,
    const float* __restrict__ W_hh, const float* __restrict__ b_hh,
    const float* __restrict__ W_pd, const float* __restrict__ b_pd,
    const float* __restrict__ W_pld,const float* __restrict__ b_pld,
    const float* __restrict__ W_pq, const float* __restrict__ b_pq,
    const float* __restrict__ W_pr, const float* __restrict__ b_pr,
    const float* __restrict__ attn_W)
{
    int tid  = blockIdx.x * blockDim.x + threadIdx.x;
    int nthr = gridDim.x * blockDim.x;

    for (int idx = tid; idx < H*O5; idx += nthr) {
        int k = idx / O5, o = idx % O5;
        d_Wt[idx] = (o < 512) ? W_hh[o*H + k] : W_pq[(o-512)*H + k];
    }
    for (int h = tid; h < H; h += nthr) {
        double ms0=0, ms1=0, wld=0, wd=0, bb=0;
        for (int k = 0; k < H; k++) {
            double wpr  = (double)W_pr [h*H+k];
            double wpld = (double)W_pld[h*H+k];
            double wpd  = (double)W_pd [h*H+k];
            ms0 += wpr  * (double)W_s[k*2+0];
            ms1 += wpr  * (double)W_s[k*2+1];
            wld += wpld * ((double)W_ld[k*2+0] + (double)W_ld[k*2+1]);
            wd  += wpd  * ((double)W_d [k*2+0] + (double)W_d [k*2+1]);
            bb  += wpr*(double)b_s[k] + wpld*(double)b_ld[k] + wpd*(double)b_d[k];
        }
        bb += (double)b_pr[h] + (double)b_pld[h] + (double)b_pd[h] + (double)b_pq[h];
        d_A4[h]    = make_float4((float)ms0, (float)ms1, (float)wld, (float)wd);
        d_cbias[h] = (float)bb;
        d_aW[h]    = attn_W[h];
    }
    for (int o = tid; o < 512; o += nthr) {
        double g0=0, g1=0, gb=0;
        for (int k = 0; k < H; k++) {
            double w = (double)W_ih[o*H+k];
            g0 += w * (double)W_s[k*2+0];
            g1 += w * (double)W_s[k*2+1];
            gb += w * (double)b_s[k];
        }
        d_G2[o*2+0] = (float)g0; d_G2[o*2+1] = (float)g1;
        d_gb[o]     = (float)(gb + (double)b_ih[o] + (double)b_hh[o]);
    }
}

// ---------------- phase 0b: base pre-activation -> f16x2 s-pairs ------------
__global__ void precompute_base(const float* __restrict__ stat,
                                const float* __restrict__ dyn)
{
    const int b   = blockIdx.x;
    const int tid = threadIdx.x;
    __shared__ float4 us[SEQ];
    __shared__ float4 a4s[H];
    for (int s = tid; s < SEQ; s += 256) {
        int g = b * (2*SEQ);
        float s0 = stat[g + s];
        float s1 = stat[g + SEQ + s];
        float ld = dyn [g + s];
        float dm = dyn [g + SEQ + s];
        us[s] = make_float4(s0, s1, ld - dm, dm);
    }
    for (int i = tid; i < H; i += 256) a4s[i] = d_A4[i];
    __syncthreads();
    uint32* bp = d_base2 + (size_t)b * H * (SEQ/2);
    for (int idx = tid; idx < H*(SEQ/2); idx += 256) {
        int sp = idx & 63, hh = idx >> 6;
        float4 a  = a4s[hh];
        float4 u0 = us[2*sp];
        float4 u1 = us[2*sp + 1];
        float f0 = fmaf(a.x,u0.x, fmaf(a.y,u0.y, fmaf(a.z,u0.z, a.w*u0.w)));
        float f1 = fmaf(a.x,u1.x, fmaf(a.y,u1.y, fmaf(a.z,u1.z, a.w*u1.w)));
        __half2 h2 = __floats2half2_rn(f0, f1);   // lo = even s, hi = odd s
        bp[idx] = *reinterpret_cast<uint32*>(&h2);
    }
}

// ---------------- main kernel ------------------------------------------------
struct SmemLayout {
    float4 u[NB][SEQ];       // 16KB (exact pass + v update)
    float4 A4[H];            //  2KB (exact pass)
    float  ht[H*8];          //  4KB  ht[k*8+b]
    float  ct[H*8];          //  4KB
    float2 qa[NB][H];        //  8KB  {q + cbias (f32, exact), aW}
    uint2  paw[NB][H];       //  8KB  {qh2 bits (q,q f16x2), aW bits}
    float  gt[512*9];        // 18KB  gt[o*9+b]
    float  G2[512][2];       //  4KB
    float  gb[512];          //  2KB
    float  cbias[H];
    float  aW[H];
    float2 v[NB];
    float  red_m [NB][2];
    int    red_mi[NB][2];
    float  red_ds[NB][2];
};

extern __shared__ char smem_raw[];

__global__ void __launch_bounds__(NTHR, 2)
drl_main(const float* __restrict__ stat, const float* __restrict__ dyn,
         const float* __restrict__ mark, float* __restrict__ out)
{
    SmemLayout& sm = *reinterpret_cast<SmemLayout*>(smem_raw);
    const int tid = threadIdx.x;
    const int b0  = blockIdx.x * NB;

    for (int i = tid; i < H; i += NTHR) {
        sm.A4[i]    = d_A4[i];
        sm.cbias[i] = d_cbias[i];
        sm.aW[i]    = d_aW[i];
    }
    for (int i = tid; i < 512; i += NTHR) {
        sm.G2[i][0] = d_G2[i*2+0];
        sm.G2[i][1] = d_G2[i*2+1];
        sm.gb[i]    = d_gb[i];
    }
    for (int idx = tid; idx < NB*SEQ; idx += NTHR) {
        int b = idx >> 7, s = idx & 127;
        int g = (b0 + b) * (2*SEQ);
        float s0 = stat[g + s];
        float s1 = stat[g + SEQ + s];
        float ld = dyn [g + s];
        float dm = dyn [g + SEQ + s];
        sm.u[b][s] = make_float4(s0, s1, ld - dm, dm);
    }
    for (int idx = tid; idx < H*8; idx += NTHR) {
        sm.ht[idx] = 0.f;
        sm.ct[idx] = 0.f;
    }
    __syncthreads();
    if (tid < NB) sm.v[tid] = make_float2(sm.u[tid][0].x, sm.u[tid][0].y);
    if (blockIdx.x == 0 && tid == 0) out[2*BTOT*SEQ] = mark[0];
    __syncthreads();

    const int o    = tid;
    const int o2   = tid & 127;
    const int bg   = tid >> 7;
    const int warp = tid >> 5;
    const int lane = tid & 31;
    const int ab   = warp >> 1;    // attention batch
    const int ah   = warp & 1;     // attention s-half
    const float NEG_INF = __int_as_float(0xff800000);
    const float MARGIN  = 0.020f;  // covers f16 tanh worst-case bias + tie cell

    for (int t = 0; t < SEQ; t++) {
        // ---- GEMM1 (f32x2 packed; per-batch chain R4-bitwise) ----
        {
            float a0[NB];
            float g0 = sm.G2[o][0], g1 = sm.G2[o][1], gbv = sm.gb[o];
            #pragma unroll
            for (int i = 0; i < NB; i++) {
                float2 vv = sm.v[i];
                a0[i] = fmaf(g0, vv.x, fmaf(g1, vv.y, gbv));
            }
            ull ap[4];
            #pragma unroll
            for (int p = 0; p < 4; p++) ap[p] = pack2(a0[2*p], a0[2*p+1]);

            const float* wt = d_Wt + o;
            #pragma unroll 4
            for (int k = 0; k < H; k += 4) {
                float w0 = wt[(k+0)*O5];
                float w1 = wt[(k+1)*O5];
                float w2 = wt[(k+2)*O5];
                float w3 = wt[(k+3)*O5];
                ull wp[4] = { pack2(w0,w0), pack2(w1,w1), pack2(w2,w2), pack2(w3,w3) };
                #pragma unroll
                for (int kk = 0; kk < 4; kk++) {
                    ulonglong2 hA = *reinterpret_cast<const ulonglong2*>(&sm.ht[(k+kk)*8]);
                    ulonglong2 hB = *reinterpret_cast<const ulonglong2*>(&sm.ht[(k+kk)*8+4]);
                    ap[0] = fma2(wp[kk], hA.x, ap[0]);
                    ap[1] = fma2(wp[kk], hA.y, ap[1]);
                    ap[2] = fma2(wp[kk], hB.x, ap[2]);
                    ap[3] = fma2(wp[kk], hB.y, ap[3]);
                }
            }
            #pragma unroll
            for (int p = 0; p < 4; p++) {
                float x, y;
                unpack2(ap[p], x, y);
                sm.gt[o*9 + 2*p    ] = x;
                sm.gt[o*9 + 2*p + 1] = y;
            }
        }
        __syncthreads();

        // ---- LSTM pointwise (R4-bitwise math) ----
        #pragma unroll
        for (int r = 0; r < (NB*H)/NTHR; r++) {
            int idx = tid + r*NTHR;
            int b = idx & 7, j = idx >> 3;
            float gi = sm.gt[(j      )*9 + b];
            float gf = sm.gt[(j + 128)*9 + b];
            float gg = sm.gt[(j + 256)*9 + b];
            float go = sm.gt[(j + 384)*9 + b];
            float c2 = sig_acc(gf) * sm.ct[j*8+b] + sig_acc(gi) * tanh_acc(gg);
            float h2 = sig_acc(go) * tanh_acc(c2);
            sm.ct[j*8+b] = c2;
            sm.ht[j*8+b] = h2;
        }
        __syncthreads();

        // ---- GEMM2 (f32x2 packed; per-batch chain R4-bitwise) ----
        {
            float cb = sm.cbias[o2];
            ull acc2 = pack2(cb, cb);
            const float* wt = d_Wt + 512 + o2;
            #pragma unroll 4
            for (int k = 0; k < H; k += 4) {
                float w0 = wt[(k+0)*O5];
                float w1 = wt[(k+1)*O5];
                float w2 = wt[(k+2)*O5];
                float w3 = wt[(k+3)*O5];
                ull h0 = *reinterpret_cast<const ull*>(&sm.ht[(k+0)*8 + bg*2]);
                ull h1 = *reinterpret_cast<const ull*>(&sm.ht[(k+1)*8 + bg*2]);
                ull h2 = *reinterpret_cast<const ull*>(&sm.ht[(k+2)*8 + bg*2]);
                ull h3 = *reinterpret_cast<const ull*>(&sm.ht[(k+3)*8 + bg*2]);
                acc2 = fma2(pack2(w0,w0), h0, acc2);
                acc2 = fma2(pack2(w1,w1), h1, acc2);
                acc2 = fma2(pack2(w2,w2), h2, acc2);
                acc2 = fma2(pack2(w3,w3), h3, acc2);
            }
            float qx, qy;
            unpack2(acc2, qx, qy);
            float aw = sm.aW[o2];
            sm.qa[bg*2    ][o2] = make_float2(qx, aw);
            sm.qa[bg*2 + 1][o2] = make_float2(qy, aw);
            __half2 qh0 = __float2half2_rn(qx);
            __half2 qh1 = __float2half2_rn(qy);
            sm.paw[bg*2    ][o2] = make_uint2(*reinterpret_cast<uint32*>(&qh0),
                                             __float_as_uint(aw));
            sm.paw[bg*2 + 1][o2] = make_uint2(*reinterpret_cast<uint32*>(&qh1),
                                             __float_as_uint(aw));
        }
        __syncthreads();

        // ---- attention: f16x2 cheap pass + exact fp64 candidates ----
        {
            const int b     = ab;
            const int sbase = ah*64 + lane*2;
            const int sp    = ah*32 + lane;          // s-pair index
            const uint32* bp = d_base2 + ((size_t)(b0 + b) * H) * (SEQ/2) + sp;
            float c0 = 0.f, c1 = 0.f;
            #pragma unroll 8
            for (int hh = 0; hh < H; hh++) {
                uint32 bz = bp[hh*(SEQ/2)];          // base pair (s even, s odd)
                uint2  pa = sm.paw[b][hh];           // {(q,q) f16x2, aw}
                uint32 z2 = hadd2u(bz, pa.x);
                uint32 t2 = tanh2u(z2);
                float2 tf = __half22float2(*reinterpret_cast<__half2*>(&t2));
                float  aw = __uint_as_float(pa.y);
                c0 = fmaf(aw, tf.x, c0);
                c1 = fmaf(aw, tf.y, c1);
            }
            if (ah == 0 && lane == 0) c0 = NEG_INF;  // masked s=0

            float cm = fmaxf(c0, c1);
            #pragma unroll
            for (int off = 16; off; off >>= 1)
                cm = fmaxf(cm, __shfl_xor_sync(0xffffffffu, cm, off));

            unsigned bal0 = __ballot_sync(0xffffffffu, c0 >= cm - MARGIN);
            unsigned bal1 = __ballot_sync(0xffffffffu, c1 >= cm - MARGIN);

            // exact recompute (R4-bitwise z chain, fp64 warp tree)
            #pragma unroll
            for (int j = 0; j < 2; j++) {
                unsigned msk = j ? bal1 : bal0;
                while (msk) {
                    int sl = __ffs(msk) - 1;
                    msk &= msk - 1;
                    int s = ah*64 + sl*2 + j;
                    float4 us = sm.u[b][s];
                    double p = 0.0;
                    #pragma unroll
                    for (int r = 0; r < 4; r++) {
                        int hh = lane + r*32;
                        float4 a  = sm.A4[hh];
                        float2 qa = sm.qa[b][hh];
                        float z = fmaf(a.x,us.x, fmaf(a.y,us.y, fmaf(a.z,us.z, fmaf(a.w,us.w, qa.x))));
                        p += (double)(qa.y * tanh_acc(z));
                    }
                    #pragma unroll
                    for (int off = 16; off; off >>= 1)
                        p += __shfl_xor_sync(0xffffffffu, p, off);
                    if (lane == sl) { if (j) c1 = (float)p; else c0 = (float)p; }
                }
            }

            float aq0 = c0 + 10000.0f;
            float aq1 = c1 + 10000.0f;

            float m  = aq0;
            int   mi = sbase;
            if (aq1 > m) { m = aq1; mi = sbase + 1; }
            #pragma unroll
            for (int off = 16; off; off >>= 1) {
                float om = __shfl_xor_sync(0xffffffffu, m,  off);
                int   oi = __shfl_xor_sync(0xffffffffu, mi, off);
                if (om > m || (om == m && oi < mi)) { m = om; mi = oi; }
            }
            float d0 = aq0 - m, d1 = aq1 - m;
            float dsum = ((d0 == NEG_INF) ? 0.f : exp_acc(d0))
                       + ((d1 == NEG_INF) ? 0.f : exp_acc(d1));
            #pragma unroll
            for (int off = 16; off; off >>= 1)
                dsum += __shfl_xor_sync(0xffffffffu, dsum, off);

            if (lane == 0) {
                sm.red_m [b][ah] = m;
                sm.red_mi[b][ah] = mi;
                sm.red_ds[b][ah] = dsum;
            }
        }
        __syncthreads();

        // ---- combine halves, emit outputs, update dec ----
        if (tid < NB) {
            const int b = tid;
            float m0 = sm.red_m[b][0], m1 = sm.red_m[b][1];
            int  mi0 = sm.red_mi[b][0], mi1 = sm.red_mi[b][1];
            float dd0 = sm.red_ds[b][0], dd1 = sm.red_ds[b][1];
            float m; int mi;
            if (m1 > m0 || (m1 == m0 && mi1 < mi0)) { m = m1; mi = mi1; }
            else                                    { m = m0; mi = mi0; }
            float dsum = dd0 * exp_acc(m0 - m) + dd1 * exp_acc(m1 - m);
            out[(b0 + b)*SEQ + t]            = (float)mi;
            out[BTOT*SEQ + (b0 + b)*SEQ + t] = -logf(dsum);
            sm.v[b] = make_float2(sm.u[b][mi].x, sm.u[b][mi].y);
        }
        __syncthreads();
    }
}

// ---------------- launch --------------------------------------------------
extern "C" void kernel_launch(void* const* d_in, const int* in_sizes, int n_in,
                              void* d_out, int out_size)
{
    (void)in_sizes; (void)n_in; (void)out_size;
    const float* stat  = (const float*)d_in[0];
    const float* dyn   = (const float*)d_in[1];
    const float* mark  = (const float*)d_in[2];
    const float* W_s   = (const float*)d_in[3];
    const float* b_s   = (const float*)d_in[4];
    const float* W_ld  = (const float*)d_in[5];
    const float* b_ld  = (const float*)d_in[6];
    const float* W_d   = (const float*)d_in[7];
    const float* b_d   = (const float*)d_in[8];
    const float* W_ih  = (const float*)d_in[9];
    const float* b_ih  = (const float*)d_in[10];
    const float* W_hh  = (const float*)d_in[11];
    const float* b_hh  = (const float*)d_in[12];
    const float* W_pd  = (const float*)d_in[13];
    const float* b_pd  = (const float*)d_in[14];
    const float* W_pld = (const float*)d_in[15];
    const float* b_pld = (const float*)d_in[16];
    const float* W_pq  = (const float*)d_in[17];
    const float* b_pq  = (const float*)d_in[18];
    const float* W_pr  = (const float*)d_in[19];
    const float* b_pr  = (const float*)d_in[20];
    const float* attn_W= (const float*)d_in[21];
    float* out = (float*)d_out;

    cudaFuncSetAttribute(drl_main, cudaFuncAttributeMaxDynamicSharedMemorySize,
                         (int)sizeof(SmemLayout));

    precompute_kernel<<<84, 512>>>(W_s, b_s, W_ld, b_ld, W_d, b_d,
                                   W_ih, b_ih, W_hh, b_hh,
                                   W_pd, b_pd, W_pld, b_pld,
                                   W_pq, b_pq, W_pr, b_pr, attn_W);

    precompute_base<<<BTOT, 256>>>(stat, dyn);

    drl_main<<<NBLK, NTHR, sizeof(SmemLayout)>>>(stat, dyn, mark, out);
}

// round 13
// speedup vs baseline: 1.8638x; 1.8638x over previous
#include <cuda_runtime.h>
#include <cuda_fp16.h>
#include <math.h>

#define H    128
#define SEQ  128
#define BTOT 2048
#define NB   8             // batches per block
#define NBLK (BTOT/NB)     // 256 blocks
#define NTHR 512
#define O5   640           // 512 (W_hh cols) + 128 (W_pq cols), transposed layout

typedef unsigned long long ull;
typedef unsigned int uint32;

// ---------------- device-global scratch -------------------------------------
__device__ float  d_Wt[H*O5];
__device__ float4 d_A4[H];
__device__ float  d_cbias[H];
__device__ float  d_aW[H];
__device__ float  d_G2[512*2];
__device__ float  d_gb[512];
__device__ float  d_base[(size_t)BTOT*H*SEQ];   // 128 MiB: t-invariant attention pre-activation

// ---------------- f32x2 packed helpers --------------------------------------
__device__ __forceinline__ ull pack2(float x, float y) {
    ull r; asm("mov.b64 %0, {%1,%2};" : "=l"(r) : "f"(x), "f"(y)); return r;
}
__device__ __forceinline__ ull fma2(ull a, ull b, ull c) {
    ull d; asm("fma.rn.f32x2 %0, %1, %2, %3;" : "=l"(d) : "l"(a), "l"(b), "l"(c)); return d;
}
__device__ __forceinline__ void unpack2(ull p, float& x, float& y) {
    asm("mov.b64 {%0,%1}, %2;" : "=f"(x), "=f"(y) : "l"(p));
}
// one-MUFU dual tanh: f32 pair -> f16x2 -> tanh -> f32 pair
__device__ __forceinline__ void tanh2_fast(float z0, float z1, float& t0, float& t1) {
    uint32 z2, t2;
    asm("cvt.rn.f16x2.f32 %0, %1, %2;" : "=r"(z2) : "f"(z1), "f"(z0));
    asm("tanh.approx.f16x2 %0, %1;"    : "=r"(t2) : "r"(z2));
    asm("{ .reg .f16 lo, hi; mov.b32 {lo, hi}, %2; cvt.f32.f16 %0, lo; cvt.f32.f16 %1, hi; }"
        : "=f"(t0), "=f"(t1) : "r"(t2));
}

// ---------------- exact transcendentals (R4-bitwise) ------------------------
__device__ __forceinline__ float exp_acc(float y) {
    const float L2E_HI = 1.44269502162933349609375f;
    const float L2E_LO = 1.9259629911266175e-8f;
    float p  = y * L2E_HI;
    float e  = fmaf(y, L2E_HI, -p);
    float pc = fminf(fmaxf(p, -126.0f), 126.0f);
    float nf = rintf(pc);
    int   ni = (int)nf;
    float f  = (pc - nf) + fmaf(y, L2E_LO, e);
    float r  = 1.5252733e-5f;
    r = fmaf(r, f, 1.5403530e-4f);
    r = fmaf(r, f, 1.3333558e-3f);
    r = fmaf(r, f, 9.6181291e-3f);
    r = fmaf(r, f, 5.5504109e-2f);
    r = fmaf(r, f, 2.4022651e-1f);
    r = fmaf(r, f, 6.9314718e-1f);
    r = fmaf(r, f, 1.0f);
    float sc = __int_as_float((ni + 127) << 23);
    return r * sc;
}
__device__ __forceinline__ float rcp_nr(float d) {
    float r;
    asm("rcp.approx.f32 %0, %1;" : "=f"(r) : "f"(d));
    return r * fmaf(-d, r, 2.0f);
}
__device__ __forceinline__ float tanh_acc(float x) {
    float E = exp_acc(x + x);
    float q = rcp_nr(E + 1.0f);
    return 1.0f - (q + q);
}
__device__ __forceinline__ float sig_acc(float x) {
    return rcp_nr(1.0f + exp_acc(-x));
}

// ---------------- phase 0: fold affine algebra (fp64) — UNCHANGED -----------
__global__ void precompute_kernel(
    const float* __restrict__ W_s,  const float* __restrict__ b_s,
    const float* __restrict__ W_ld, const float* __restrict__ b_ld,
    const float* __restrict__ W_d,  const float* __restrict__ b_d,
    const float* __restrict__ W_ih, const float* __restrict__ b_ih,
    const float* __restrict__ W_hh, const float* __restrict__ b_hh,
    const float* __restrict__ W_pd, const float* __restrict__ b_pd,
    const float* __restrict__ W_pld,const float* __restrict__ b_pld,
    const float* __restrict__ W_pq, const float* __restrict__ b_pq,
    const float* __restrict__ W_pr, const float* __restrict__ b_pr,
    const float* __restrict__ attn_W)
{
    int tid  = blockIdx.x * blockDim.x + threadIdx.x;
    int nthr = gridDim.x * blockDim.x;

    for (int idx = tid; idx < H*O5; idx += nthr) {
        int k = idx / O5, o = idx % O5;
        d_Wt[idx] = (o < 512) ? W_hh[o*H + k] : W_pq[(o-512)*H + k];
    }
    for (int h = tid; h < H; h += nthr) {
        double ms0=0, ms1=0, wld=0, wd=0, bb=0;
        for (int k = 0; k < H; k++) {
            double wpr  = (double)W_pr [h*H+k];
            double wpld = (double)W_pld[h*H+k];
            double wpd  = (double)W_pd [h*H+k];
            ms0 += wpr  * (double)W_s[k*2+0];
            ms1 += wpr  * (double)W_s[k*2+1];
            wld += wpld * ((double)W_ld[k*2+0] + (double)W_ld[k*2+1]);
            wd  += wpd  * ((double)W_d [k*2+0] + (double)W_d [k*2+1]);
            bb  += wpr*(double)b_s[k] + wpld*(double)b_ld[k] + wpd*(double)b_d[k];
        }
        bb += (double)b_pr[h] + (double)b_pld[h] + (double)b_pd[h] + (double)b_pq[h];
        d_A4[h]    = make_float4((float)ms0, (float)ms1, (float)wld, (float)wd);
        d_cbias[h] = (float)bb;
        d_aW[h]    = attn_W[h];
    }
    for (int o = tid; o < 512; o += nthr) {
        double g0=0, g1=0, gb=0;
        for (int k = 0; k < H; k++) {
            double w = (double)W_ih[o*H+k];
            g0 += w * (double)W_s[k*2+0];
            g1 += w * (double)W_s[k*2+1];
            gb += w * (double)b_s[k];
        }
        d_G2[o*2+0] = (float)g0; d_G2[o*2+1] = (float)g1;
        d_gb[o]     = (float)(gb + (double)b_ih[o] + (double)b_hh[o]);
    }
}

// ---------------- phase 0b: t-invariant attention pre-activation (f32) ------
__global__ void precompute_base(const float* __restrict__ stat,
                                const float* __restrict__ dyn)
{
    const int b   = blockIdx.x;
    const int tid = threadIdx.x;
    __shared__ float4 us[SEQ];
    __shared__ float4 a4s[H];
    for (int s = tid; s < SEQ; s += 256) {
        int g = b * (2*SEQ);
        float s0 = stat[g + s];
        float s1 = stat[g + SEQ + s];
        float ld = dyn [g + s];
        float dm = dyn [g + SEQ + s];
        us[s] = make_float4(s0, s1, ld - dm, dm);
    }
    for (int i = tid; i < H; i += 256) a4s[i] = d_A4[i];
    __syncthreads();
    float* bp = d_base + (size_t)b * H * SEQ;
    for (int idx = tid; idx < H*SEQ; idx += 256) {
        int s = idx & 127, hh = idx >> 7;
        float4 a = a4s[hh];
        float4 u = us[s];
        bp[idx] = fmaf(a.x,u.x, fmaf(a.y,u.y, fmaf(a.z,u.z, a.w*u.w)));
    }
}

// ---------------- main kernel ------------------------------------------------
struct SmemLayout {
    float4 u[NB][SEQ];       // 16KB (exact pass + v update)
    float4 A4[H];            //  2KB (exact pass)
    float  ht[H*8];          //  4KB  ht[k*8+b]
    float  ct[H*8];          //  4KB
    float2 qa[NB][H];        //  8KB  {q + cbias, aW}
    float  gt[512*9];        // 18KB  gt[o*9+b]
    float  G2[512][2];       //  4KB
    float  gb[512];          //  2KB
    float  cbias[H];
    float  aW[H];
    float2 v[NB];
    float  red_m [NB][2];
    int    red_mi[NB][2];
    float  red_ds[NB][2];
};

extern __shared__ char smem_raw[];

__global__ void __launch_bounds__(NTHR, 2)
drl_main(const float* __restrict__ stat, const float* __restrict__ dyn,
         const float* __restrict__ mark, float* __restrict__ out)
{
    SmemLayout& sm = *reinterpret_cast<SmemLayout*>(smem_raw);
    const int tid = threadIdx.x;
    const int b0  = blockIdx.x * NB;

    for (int i = tid; i < H; i += NTHR) {
        sm.A4[i]    = d_A4[i];
        sm.cbias[i] = d_cbias[i];
        sm.aW[i]    = d_aW[i];
    }
    for (int i = tid; i < 512; i += NTHR) {
        sm.G2[i][0] = d_G2[i*2+0];
        sm.G2[i][1] = d_G2[i*2+1];
        sm.gb[i]    = d_gb[i];
    }
    for (int idx = tid; idx < NB*SEQ; idx += NTHR) {
        int b = idx >> 7, s = idx & 127;
        int g = (b0 + b) * (2*SEQ);
        float s0 = stat[g + s];
        float s1 = stat[g + SEQ + s];
        float ld = dyn [g + s];
        float dm = dyn [g + SEQ + s];
        sm.u[b][s] = make_float4(s0, s1, ld - dm, dm);
    }
    for (int idx = tid; idx < H*8; idx += NTHR) {
        sm.ht[idx] = 0.f;
        sm.ct[idx] = 0.f;
    }
    __syncthreads();
    if (tid < NB) sm.v[tid] = make_float2(sm.u[tid][0].x, sm.u[tid][0].y);
    if (blockIdx.x == 0 && tid == 0) out[2*BTOT*SEQ] = mark[0];
    __syncthreads();

    const int o    = tid;
    const int o2   = tid & 127;
    const int bg   = tid >> 7;
    const int warp = tid >> 5;
    const int lane = tid & 31;
    const int ab   = warp >> 1;    // attention batch
    const int ah   = warp & 1;     // attention s-half
    const float NEG_INF = __int_as_float(0xff800000);
    const float MARGIN  = 0.015f;  // f16 tanh worst-case bias + tie cell

    for (int t = 0; t < SEQ; t++) {
        // ---- GEMM1 (f32x2 packed; per-batch chain R4-bitwise) ----
        {
            float a0[NB];
            float g0 = sm.G2[o][0], g1 = sm.G2[o][1], gbv = sm.gb[o];
            #pragma unroll
            for (int i = 0; i < NB; i++) {
                float2 vv = sm.v[i];
                a0[i] = fmaf(g0, vv.x, fmaf(g1, vv.y, gbv));
            }
            ull ap[4];
            #pragma unroll
            for (int p = 0; p < 4; p++) ap[p] = pack2(a0[2*p], a0[2*p+1]);

            const float* wt = d_Wt + o;
            #pragma unroll 4
            for (int k = 0; k < H; k += 4) {
                float w0 = wt[(k+0)*O5];
                float w1 = wt[(k+1)*O5];
                float w2 = wt[(k+2)*O5];
                float w3 = wt[(k+3)*O5];
                ull wp[4] = { pack2(w0,w0), pack2(w1,w1), pack2(w2,w2), pack2(w3,w3) };
                #pragma unroll
                for (int kk = 0; kk < 4; kk++) {
                    ulonglong2 hA = *reinterpret_cast<const ulonglong2*>(&sm.ht[(k+kk)*8]);
                    ulonglong2 hB = *reinterpret_cast<const ulonglong2*>(&sm.ht[(k+kk)*8+4]);
                    ap[0] = fma2(wp[kk], hA.x, ap[0]);
                    ap[1] = fma2(wp[kk], hA.y, ap[1]);
                    ap[2] = fma2(wp[kk], hB.x, ap[2]);
                    ap[3] = fma2(wp[kk], hB.y, ap[3]);
                }
            }
            #pragma unroll
            for (int p = 0; p < 4; p++) {
                float x, y;
                unpack2(ap[p], x, y);
                sm.gt[o*9 + 2*p    ] = x;
                sm.gt[o*9 + 2*p + 1] = y;
            }
        }
        __syncthreads();

        // ---- LSTM pointwise (R4-bitwise math) ----
        #pragma unroll
        for (int r = 0; r < (NB*H)/NTHR; r++) {
            int idx = tid + r*NTHR;
            int b = idx & 7, j = idx >> 3;
            float gi = sm.gt[(j      )*9 + b];
            float gf = sm.gt[(j + 128)*9 + b];
            float gg = sm.gt[(j + 256)*9 + b];
            float go = sm.gt[(j + 384)*9 + b];
            float c2 = sig_acc(gf) * sm.ct[j*8+b] + sig_acc(gi) * tanh_acc(gg);
            float h2 = sig_acc(go) * tanh_acc(c2);
            sm.ct[j*8+b] = c2;
            sm.ht[j*8+b] = h2;
        }
        __syncthreads();

        // ---- GEMM2 (f32x2 packed; per-batch chain R4-bitwise) ----
        {
            float cb = sm.cbias[o2];
            ull acc2 = pack2(cb, cb);
            const float* wt = d_Wt + 512 + o2;
            #pragma unroll 4
            for (int k = 0; k < H; k += 4) {
                float w0 = wt[(k+0)*O5];
                float w1 = wt[(k+1)*O5];
                float w2 = wt[(k+2)*O5];
                float w3 = wt[(k+3)*O5];
                ull h0 = *reinterpret_cast<const ull*>(&sm.ht[(k+0)*8 + bg*2]);
                ull h1 = *reinterpret_cast<const ull*>(&sm.ht[(k+1)*8 + bg*2]);
                ull h2 = *reinterpret_cast<const ull*>(&sm.ht[(k+2)*8 + bg*2]);
                ull h3 = *reinterpret_cast<const ull*>(&sm.ht[(k+3)*8 + bg*2]);
                acc2 = fma2(pack2(w0,w0), h0, acc2);
                acc2 = fma2(pack2(w1,w1), h1, acc2);
                acc2 = fma2(pack2(w2,w2), h2, acc2);
                acc2 = fma2(pack2(w3,w3), h3, acc2);
            }
            float qx, qy;
            unpack2(acc2, qx, qy);
            float aw = sm.aW[o2];
            sm.qa[bg*2    ][o2] = make_float2(qx, aw);
            sm.qa[bg*2 + 1][o2] = make_float2(qy, aw);
        }
        __syncthreads();

        // ---- attention: cheap pass (1 MUFU per hh via f16x2) + exact candidates ----
        {
            const int b     = ab;
            const int sbase = ah*64 + lane*2;
            const float* bp = d_base + ((size_t)(b0 + b) * H) * SEQ + sbase;
            float c0 = 0.f, c1 = 0.f;
            #pragma unroll 8
            for (int hh = 0; hh < H; hh++) {
                float2 bs = *reinterpret_cast<const float2*>(bp + hh*SEQ);
                float2 qa = sm.qa[b][hh];
                float t0, t1;
                tanh2_fast(bs.x + qa.x, bs.y + qa.x, t0, t1);
                c0 = fmaf(qa.y, t0, c0);
                c1 = fmaf(qa.y, t1, c1);
            }
            if (ah == 0 && lane == 0) c0 = NEG_INF;   // masked s=0

            float cm = fmaxf(c0, c1);
            #pragma unroll
            for (int off = 16; off; off >>= 1)
                cm = fmaxf(cm, __shfl_xor_sync(0xffffffffu, cm, off));

            unsigned bal0 = __ballot_sync(0xffffffffu, c0 >= cm - MARGIN);
            unsigned bal1 = __ballot_sync(0xffffffffu, c1 >= cm - MARGIN);

            // exact recompute (R4-bitwise z chain, fp64 warp tree)
            #pragma unroll
            for (int j = 0; j < 2; j++) {
                unsigned msk = j ? bal1 : bal0;
                while (msk) {
                    int sl = __ffs(msk) - 1;
                    msk &= msk - 1;
                    int s = ah*64 + sl*2 + j;
                    float4 us = sm.u[b][s];
                    double p = 0.0;
                    #pragma unroll
                    for (int r = 0; r < 4; r++) {
                        int hh = lane + r*32;
                        float4 a  = sm.A4[hh];
                        float2 qa = sm.qa[b][hh];
                        float z = fmaf(a.x,us.x, fmaf(a.y,us.y, fmaf(a.z,us.z, fmaf(a.w,us.w, qa.x))));
                        p += (double)(qa.y * tanh_acc(z));
                    }
                    #pragma unroll
                    for (int off = 16; off; off >>= 1)
                        p += __shfl_xor_sync(0xffffffffu, p, off);
                    if (lane == sl) { if (j) c1 = (float)p; else c0 = (float)p; }
                }
            }

            float aq0 = c0 + 10000.0f;
            float aq1 = c1 + 10000.0f;

            float m  = aq0;
            int   mi = sbase;
            if (aq1 > m) { m = aq1; mi = sbase + 1; }
            #pragma unroll
            for (int off = 16; off; off >>= 1) {
                float om = __shfl_xor_sync(0xffffffffu, m,  off);
                int   oi = __shfl_xor_sync(0xffffffffu, mi, off);
                if (om > m || (om == m && oi < mi)) { m = om; mi = oi; }
            }
            float d0 = aq0 - m, d1 = aq1 - m;
            float dsum = ((d0 == NEG_INF) ? 0.f : exp_acc(d0))
                       + ((d1 == NEG_INF) ? 0.f : exp_acc(d1));
            #pragma unroll
            for (int off = 16; off; off >>= 1)
                dsum += __shfl_xor_sync(0xffffffffu, dsum, off);

            if (lane == 0) {
                sm.red_m [b][ah] = m;
                sm.red_mi[b][ah] = mi;
                sm.red_ds[b][ah] = dsum;
            }
        }
        __syncthreads();

        // ---- combine halves, emit outputs, update dec ----
        if (tid < NB) {
            const int b = tid;
            float m0 = sm.red_m[b][0], m1 = sm.red_m[b][1];
            int  mi0 = sm.red_mi[b][0], mi1 = sm.red_mi[b][1];
            float dd0 = sm.red_ds[b][0], dd1 = sm.red_ds[b][1];
            float m; int mi;
            if (m1 > m0 || (m1 == m0 && mi1 < mi0)) { m = m1; mi = mi1; }
            else                                    { m = m0; mi = mi0; }
            float dsum = dd0 * exp_acc(m0 - m) + dd1 * exp_acc(m1 - m);
            out[(b0 + b)*SEQ + t]            = (float)mi;
            out[BTOT*SEQ + (b0 + b)*SEQ + t] = -logf(dsum);
            sm.v[b] = make_float2(sm.u[b][mi].x, sm.u[b][mi].y);
        }
        __syncthreads();
    }
}

// ---------------- launch --------------------------------------------------
extern "C" void kernel_launch(void* const* d_in, const int* in_sizes, int n_in,
                              void* d_out, int out_size)
{
    (void)in_sizes; (void)n_in; (void)out_size;
    const float* stat  = (const float*)d_in[0];
    const float* dyn   = (const float*)d_in[1];
    const float* mark  = (const float*)d_in[2];
    const float* W_s   = (const float*)d_in[3];
    const float* b_s   = (const float*)d_in[4];
    const float* W_ld  = (const float*)d_in[5];
    const float* b_ld  = (const float*)d_in[6];
    const float* W_d   = (const float*)d_in[7];
    const float* b_d   = (const float*)d_in[8];
    const float* W_ih  = (const float*)d_in[9];
    const float* b_ih  = (const float*)d_in[10];
    const float* W_hh  = (const float*)d_in[11];
    const float* b_hh  = (const float*)d_in[12];
    const float* W_pd  = (const float*)d_in[13];
    const float* b_pd  = (const float*)d_in[14];
    const float* W_pld = (const float*)d_in[15];
    const float* b_pld = (const float*)d_in[16];
    const float* W_pq  = (const float*)d_in[17];
    const float* b_pq  = (const float*)d_in[18];
    const float* W_pr  = (const float*)d_in[19];
    const float* b_pr  = (const float*)d_in[20];
    const float* attn_W= (const float*)d_in[21];
    float* out = (float*)d_out;

    cudaFuncSetAttribute(drl_main, cudaFuncAttributeMaxDynamicSharedMemorySize,
                         (int)sizeof(SmemLayout));

    precompute_kernel<<<84, 512>>>(W_s, b_s, W_ld, b_ld, W_d, b_d,
                                   W_ih, b_ih, W_hh, b_hh,
                                   W_pd, b_pd, W_pld, b_pld,
                                   W_pq, b_pq, W_pr, b_pr, attn_W);

    precompute_base<<<BTOT, 256>>>(stat, dyn);

    drl_main<<<NBLK, NTHR, sizeof(SmemLayout)>>>(stat, dyn, mark, out);
}

// round 14
// speedup vs baseline: 1.9583x; 1.0507x over previous
#include <cuda_runtime.h>
#include <cuda_fp16.h>
#include <math.h>

#define H    128
#define SEQ  128
#define BTOT 2048
#define NB   8             // batches per block
#define NBLK (BTOT/NB)     // 256 blocks
#define NTHR 512
#define O5   640           // 512 (W_hh cols) + 128 (W_pq cols), transposed layout

typedef unsigned long long ull;
typedef unsigned int uint32;

// ---------------- device-global scratch -------------------------------------
__device__ float  d_Wt[H*O5];
__device__ float4 d_A4[H];
__device__ float  d_cbias[H];
__device__ float  d_aW[H];
__device__ float  d_G2[512*2];
__device__ float  d_gb[512];
// t-invariant attention pre-activation, f16x2 s-pairs: [b][hh][s/2] -> 64 MiB (L2-resident)
__device__ uint32 d_base2[(size_t)BTOT*H*(SEQ/2)];

// ---------------- f32x2 packed helpers --------------------------------------
__device__ __forceinline__ ull pack2(float x, float y) {
    ull r; asm("mov.b64 %0, {%1,%2};" : "=l"(r) : "f"(x), "f"(y)); return r;
}
__device__ __forceinline__ ull fma2(ull a, ull b, ull c) {
    ull d; asm("fma.rn.f32x2 %0, %1, %2, %3;" : "=l"(d) : "l"(a), "l"(b), "l"(c)); return d;
}
__device__ __forceinline__ void unpack2(ull p, float& x, float& y) {
    asm("mov.b64 {%0,%1}, %2;" : "=f"(x), "=f"(y) : "l"(p));
}
// f16x2 pair -> two f32 (load-side decompress only; all math stays f32)
__device__ __forceinline__ void h2_to_f32(uint32 h2, float& x, float& y) {
    asm("{ .reg .f16 lo, hi; mov.b32 {lo, hi}, %2; cvt.f32.f16 %0, lo; cvt.f32.f16 %1, hi; }"
        : "=f"(x), "=f"(y) : "r"(h2));
}
// cheap HW tanh (MUFU.TANH f32) for the bulk attention pass — R11-proven
__device__ __forceinline__ float tanh_fast(float x) {
    float y;
    asm("tanh.approx.f32 %0, %1;" : "=f"(y) : "f"(x));
    return y;
}

// ---------------- exact transcendentals (R4-bitwise) ------------------------
__device__ __forceinline__ float exp_acc(float y) {
    const float L2E_HI = 1.44269502162933349609375f;
    const float L2E_LO = 1.9259629911266175e-8f;
    float p  = y * L2E_HI;
    float e  = fmaf(y, L2E_HI, -p);
    float pc = fminf(fmaxf(p, -126.0f), 126.0f);
    float nf = rintf(pc);
    int   ni = (int)nf;
    float f  = (pc - nf) + fmaf(y, L2E_LO, e);
    float r  = 1.5252733e-5f;
    r = fmaf(r, f, 1.5403530e-4f);
    r = fmaf(r, f, 1.3333558e-3f);
    r = fmaf(r, f, 9.6181291e-3f);
    r = fmaf(r, f, 5.5504109e-2f);
    r = fmaf(r, f, 2.4022651e-1f);
    r = fmaf(r, f, 6.9314718e-1f);
    r = fmaf(r, f, 1.0f);
    float sc = __int_as_float((ni + 127) << 23);
    return r * sc;
}
__device__ __forceinline__ float rcp_nr(float d) {
    float r;
    asm("rcp.approx.f32 %0, %1;" : "=f"(r) : "f"(d));
    return r * fmaf(-d, r, 2.0f);
}
__device__ __forceinline__ float tanh_acc(float x) {
    float E = exp_acc(x + x);
    float q = rcp_nr(E + 1.0f);
    return 1.0f - (q + q);
}
__device__ __forceinline__ float sig_acc(float x) {
    return rcp_nr(1.0f + exp_acc(-x));
}

// ---------------- phase 0: fold affine algebra (fp64) — UNCHANGED -----------
__global__ void precompute_kernel(
    const float* __restrict__ W_s,  const float* __restrict__ b_s,
    const float* __restrict__ W_ld, const float* __restrict__ b_ld,
    const float* __restrict__ W_d,  const float* __restrict__ b_d,
    const float* __restrict__ W_ih, const float* __restrict__ b_ih,
    const float* __restrict__ W_hh, const float* __restrict__ b_hh,
    const float* __restrict__ W_pd, const float* __restrict__ b_pd,
    const float* __restrict__ W_pld,const float* __restrict__ b_pld,
    const float* __restrict__ W_pq, const float* __restrict__ b_pq,
    const float* __restrict__ W_pr, const float* __restrict__ b_pr,
    const float* __restrict__ attn_W)
{
    int tid  = blockIdx.x * blockDim.x + threadIdx.x;
    int nthr = gridDim.x * blockDim.x;

    for (int idx = tid; idx < H*O5; idx += nthr) {
        int k = idx / O5, o = idx % O5;
        d_Wt[idx] = (o < 512) ? W_hh[o*H + k] : W_pq[(o-512)*H + k];
    }
    for (int h = tid; h < H; h += nthr) {
        double ms0=0, ms1=0, wld=0, wd=0, bb=0;
        for (int k = 0; k < H; k++) {
            double wpr  = (double)W_pr [h*H+k];
            double wpld = (double)W_pld[h*H+k];
            double wpd  = (double)W_pd [h*H+k];
            ms0 += wpr  * (double)W_s[k*2+0];
            ms1 += wpr  * (double)W_s[k*2+1];
            wld += wpld * ((double)W_ld[k*2+0] + (double)W_ld[k*2+1]);
            wd  += wpd  * ((double)W_d [k*2+0] + (double)W_d [k*2+1]);
            bb  += wpr*(double)b_s[k] + wpld*(double)b_ld[k] + wpd*(double)b_d[k];
        }
        bb += (double)b_pr[h] + (double)b_pld[h] + (double)b_pd[h] + (double)b_pq[h];
        d_A4[h]    = make_float4((float)ms0, (float)ms1, (float)wld, (float)wd);
        d_cbias[h] = (float)bb;
        d_aW[h]    = attn_W[h];
    }
    for (int o = tid; o < 512; o += nthr) {
        double g0=0, g1=0, gb=0;
        for (int k = 0; k < H; k++) {
            double w = (double)W_ih[o*H+k];
            g0 += w * (double)W_s[k*2+0];
            g1 += w * (double)W_s[k*2+1];
            gb += w * (double)b_s[k];
        }
        d_G2[o*2+0] = (float)g0; d_G2[o*2+1] = (float)g1;
        d_gb[o]     = (float)(gb + (double)b_ih[o] + (double)b_hh[o]);
    }
}

// ---------------- phase 0b: base pre-activation -> f16x2 s-pairs ------------
__global__ void precompute_base(const float* __restrict__ stat,
                                const float* __restrict__ dyn)
{
    const int b   = blockIdx.x;
    const int tid = threadIdx.x;
    __shared__ float4 us[SEQ];
    __shared__ float4 a4s[H];
    for (int s = tid; s < SEQ; s += 256) {
        int g = b * (2*SEQ);
        float s0 = stat[g + s];
        float s1 = stat[g + SEQ + s];
        float ld = dyn [g + s];
        float dm = dyn [g + SEQ + s];
        us[s] = make_float4(s0, s1, ld - dm, dm);
    }
    for (int i = tid; i < H; i += 256) a4s[i] = d_A4[i];
    __syncthreads();
    uint32* bp = d_base2 + (size_t)b * H * (SEQ/2);
    for (int idx = tid; idx < H*(SEQ/2); idx += 256) {
        int sp = idx & 63, hh = idx >> 6;
        float4 a  = a4s[hh];
        float4 u0 = us[2*sp];
        float4 u1 = us[2*sp + 1];
        float f0 = fmaf(a.x,u0.x, fmaf(a.y,u0.y, fmaf(a.z,u0.z, a.w*u0.w)));
        float f1 = fmaf(a.x,u1.x, fmaf(a.y,u1.y, fmaf(a.z,u1.z, a.w*u1.w)));
        __half2 h2 = __floats2half2_rn(f0, f1);   // lo = even s, hi = odd s
        bp[idx] = *reinterpret_cast<uint32*>(&h2);
    }
}

// ---------------- main kernel ------------------------------------------------
struct SmemLayout {
    float4 u[NB][SEQ];       // 16KB (exact pass + v update)
    float4 A4[H];            //  2KB (exact pass)
    float  ht[H*8];          //  4KB  ht[k*8+b]
    float  ct[H*8];          //  4KB
    float2 qa[NB][H];        //  8KB  {q + cbias, aW}
    float  gt[512*9];        // 18KB  gt[o*9+b]
    float  G2[512][2];       //  4KB
    float  gb[512];          //  2KB
    float  cbias[H];
    float  aW[H];
    float2 v[NB];
    float  red_m [NB][2];
    int    red_mi[NB][2];
    float  red_ds[NB][2];
};

extern __shared__ char smem_raw[];

__global__ void __launch_bounds__(NTHR, 2)
drl_main(const float* __restrict__ stat, const float* __restrict__ dyn,
         const float* __restrict__ mark, float* __restrict__ out)
{
    SmemLayout& sm = *reinterpret_cast<SmemLayout*>(smem_raw);
    const int tid = threadIdx.x;
    const int b0  = blockIdx.x * NB;

    for (int i = tid; i < H; i += NTHR) {
        sm.A4[i]    = d_A4[i];
        sm.cbias[i] = d_cbias[i];
        sm.aW[i]    = d_aW[i];
    }
    for (int i = tid; i < 512; i += NTHR) {
        sm.G2[i][0] = d_G2[i*2+0];
        sm.G2[i][1] = d_G2[i*2+1];
        sm.gb[i]    = d_gb[i];
    }
    for (int idx = tid; idx < NB*SEQ; idx += NTHR) {
        int b = idx >> 7, s = idx & 127;
        int g = (b0 + b) * (2*SEQ);
        float s0 = stat[g + s];
        float s1 = stat[g + SEQ + s];
        float ld = dyn [g + s];
        float dm = dyn [g + SEQ + s];
        sm.u[b][s] = make_float4(s0, s1, ld - dm, dm);
    }
    for (int idx = tid; idx < H*8; idx += NTHR) {
        sm.ht[idx] = 0.f;
        sm.ct[idx] = 0.f;
    }
    __syncthreads();
    if (tid < NB) sm.v[tid] = make_float2(sm.u[tid][0].x, sm.u[tid][0].y);
    if (blockIdx.x == 0 && tid == 0) out[2*BTOT*SEQ] = mark[0];
    __syncthreads();

    const int o    = tid;
    const int o2   = tid & 127;
    const int bg   = tid >> 7;
    const int warp = tid >> 5;
    const int lane = tid & 31;
    const int ab   = warp >> 1;    // attention batch
    const int ah   = warp & 1;     // attention s-half
    const float NEG_INF = __int_as_float(0xff800000);
    const float MARGIN  = 0.015f;  // cheap-tanh bias + f16 base rounding + tie cell

    for (int t = 0; t < SEQ; t++) {
        // ---- GEMM1 (f32x2 packed; per-batch chain R4-bitwise) ----
        {
            float a0[NB];
            float g0 = sm.G2[o][0], g1 = sm.G2[o][1], gbv = sm.gb[o];
            #pragma unroll
            for (int i = 0; i < NB; i++) {
                float2 vv = sm.v[i];
                a0[i] = fmaf(g0, vv.x, fmaf(g1, vv.y, gbv));
            }
            ull ap[4];
            #pragma unroll
            for (int p = 0; p < 4; p++) ap[p] = pack2(a0[2*p], a0[2*p+1]);

            const float* wt = d_Wt + o;
            #pragma unroll 4
            for (int k = 0; k < H; k += 4) {
                float w0 = wt[(k+0)*O5];
                float w1 = wt[(k+1)*O5];
                float w2 = wt[(k+2)*O5];
                float w3 = wt[(k+3)*O5];
                ull wp[4] = { pack2(w0,w0), pack2(w1,w1), pack2(w2,w2), pack2(w3,w3) };
                #pragma unroll
                for (int kk = 0; kk < 4; kk++) {
                    ulonglong2 hA = *reinterpret_cast<const ulonglong2*>(&sm.ht[(k+kk)*8]);
                    ulonglong2 hB = *reinterpret_cast<const ulonglong2*>(&sm.ht[(k+kk)*8+4]);
                    ap[0] = fma2(wp[kk], hA.x, ap[0]);
                    ap[1] = fma2(wp[kk], hA.y, ap[1]);
                    ap[2] = fma2(wp[kk], hB.x, ap[2]);
                    ap[3] = fma2(wp[kk], hB.y, ap[3]);
                }
            }
            #pragma unroll
            for (int p = 0; p < 4; p++) {
                float x, y;
                unpack2(ap[p], x, y);
                sm.gt[o*9 + 2*p    ] = x;
                sm.gt[o*9 + 2*p + 1] = y;
            }
        }
        __syncthreads();

        // ---- LSTM pointwise (R4-bitwise math) ----
        #pragma unroll
        for (int r = 0; r < (NB*H)/NTHR; r++) {
            int idx = tid + r*NTHR;
            int b = idx & 7, j = idx >> 3;
            float gi = sm.gt[(j      )*9 + b];
            float gf = sm.gt[(j + 128)*9 + b];
            float gg = sm.gt[(j + 256)*9 + b];
            float go = sm.gt[(j + 384)*9 + b];
            float c2 = sig_acc(gf) * sm.ct[j*8+b] + sig_acc(gi) * tanh_acc(gg);
            float h2 = sig_acc(go) * tanh_acc(c2);
            sm.ct[j*8+b] = c2;
            sm.ht[j*8+b] = h2;
        }
        __syncthreads();

        // ---- GEMM2 (f32x2 packed; per-batch chain R4-bitwise) ----
        {
            float cb = sm.cbias[o2];
            ull acc2 = pack2(cb, cb);
            const float* wt = d_Wt + 512 + o2;
            #pragma unroll 4
            for (int k = 0; k < H; k += 4) {
                float w0 = wt[(k+0)*O5];
                float w1 = wt[(k+1)*O5];
                float w2 = wt[(k+2)*O5];
                float w3 = wt[(k+3)*O5];
                ull h0 = *reinterpret_cast<const ull*>(&sm.ht[(k+0)*8 + bg*2]);
                ull h1 = *reinterpret_cast<const ull*>(&sm.ht[(k+1)*8 + bg*2]);
                ull h2 = *reinterpret_cast<const ull*>(&sm.ht[(k+2)*8 + bg*2]);
                ull h3 = *reinterpret_cast<const ull*>(&sm.ht[(k+3)*8 + bg*2]);
                acc2 = fma2(pack2(w0,w0), h0, acc2);
                acc2 = fma2(pack2(w1,w1), h1, acc2);
                acc2 = fma2(pack2(w2,w2), h2, acc2);
                acc2 = fma2(pack2(w3,w3), h3, acc2);
            }
            float qx, qy;
            unpack2(acc2, qx, qy);
            float aw = sm.aW[o2];
            sm.qa[bg*2    ][o2] = make_float2(qx, aw);
            sm.qa[bg*2 + 1][o2] = make_float2(qy, aw);
        }
        __syncthreads();

        // ---- attention: cheap pass (f16 base -> f32 math, 2 MUFU) + exact candidates ----
        {
            const int b     = ab;
            const int sbase = ah*64 + lane*2;
            const uint32* bp = d_base2 + ((size_t)(b0 + b) * H) * (SEQ/2) + (ah*32 + lane);
            float c0 = 0.f, c1 = 0.f;
            #pragma unroll 8
            for (int hh = 0; hh < H; hh++) {
                uint32 bz = bp[hh*(SEQ/2)];
                float2 qa = sm.qa[b][hh];
                float bx, by;
                h2_to_f32(bz, bx, by);
                c0 = fmaf(qa.y, tanh_fast(bx + qa.x), c0);
                c1 = fmaf(qa.y, tanh_fast(by + qa.x), c1);
            }
            if (ah == 0 && lane == 0) c0 = NEG_INF;   // masked s=0

            float cm = fmaxf(c0, c1);
            #pragma unroll
            for (int off = 16; off; off >>= 1)
                cm = fmaxf(cm, __shfl_xor_sync(0xffffffffu, cm, off));

            unsigned bal0 = __ballot_sync(0xffffffffu, c0 >= cm - MARGIN);
            unsigned bal1 = __ballot_sync(0xffffffffu, c1 >= cm - MARGIN);

            // exact recompute (R4-bitwise z chain, fp64 warp tree)
            #pragma unroll
            for (int j = 0; j < 2; j++) {
                unsigned msk = j ? bal1 : bal0;
                while (msk) {
                    int sl = __ffs(msk) - 1;
                    msk &= msk - 1;
                    int s = ah*64 + sl*2 + j;
                    float4 us = sm.u[b][s];
                    double p = 0.0;
                    #pragma unroll
                    for (int r = 0; r < 4; r++) {
                        int hh = lane + r*32;
                        float4 a  = sm.A4[hh];
                        float2 qa = sm.qa[b][hh];
                        float z = fmaf(a.x,us.x, fmaf(a.y,us.y, fmaf(a.z,us.z, fmaf(a.w,us.w, qa.x))));
                        p += (double)(qa.y * tanh_acc(z));
                    }
                    #pragma unroll
                    for (int off = 16; off; off >>= 1)
                        p += __shfl_xor_sync(0xffffffffu, p, off);
                    if (lane == sl) { if (j) c1 = (float)p; else c0 = (float)p; }
                }
            }

            float aq0 = c0 + 10000.0f;
            float aq1 = c1 + 10000.0f;

            float m  = aq0;
            int   mi = sbase;
            if (aq1 > m) { m = aq1; mi = sbase + 1; }
            #pragma unroll
            for (int off = 16; off; off >>= 1) {
                float om = __shfl_xor_sync(0xffffffffu, m,  off);
                int   oi = __shfl_xor_sync(0xffffffffu, mi, off);
                if (om > m || (om == m && oi < mi)) { m = om; mi = oi; }
            }
            float d0 = aq0 - m, d1 = aq1 - m;
            float dsum = ((d0 == NEG_INF) ? 0.f : exp_acc(d0))
                       + ((d1 == NEG_INF) ? 0.f : exp_acc(d1));
            #pragma unroll
            for (int off = 16; off; off >>= 1)
                dsum += __shfl_xor_sync(0xffffffffu, dsum, off);

            if (lane == 0) {
                sm.red_m [b][ah] = m;
                sm.red_mi[b][ah] = mi;
                sm.red_ds[b][ah] = dsum;
            }
        }
        __syncthreads();

        // ---- combine halves, emit outputs, update dec ----
        if (tid < NB) {
            const int b = tid;
            float m0 = sm.red_m[b][0], m1 = sm.red_m[b][1];
            int  mi0 = sm.red_mi[b][0], mi1 = sm.red_mi[b][1];
            float dd0 = sm.red_ds[b][0], dd1 = sm.red_ds[b][1];
            float m; int mi;
            if (m1 > m0 || (m1 == m0 && mi1 < mi0)) { m = m1; mi = mi1; }
            else                                    { m = m0; mi = mi0; }
            float dsum = dd0 * exp_acc(m0 - m) + dd1 * exp_acc(m1 - m);
            out[(b0 + b)*SEQ + t]            = (float)mi;
            out[BTOT*SEQ + (b0 + b)*SEQ + t] = -logf(dsum);
            sm.v[b] = make_float2(sm.u[b][mi].x, sm.u[b][mi].y);
        }
        __syncthreads();
    }
}

// ---------------- launch --------------------------------------------------
extern "C" void kernel_launch(void* const* d_in, const int* in_sizes, int n_in,
                              void* d_out, int out_size)
{
    (void)in_sizes; (void)n_in; (void)out_size;
    const float* stat  = (const float*)d_in[0];
    const float* dyn   = (const float*)d_in[1];
    const float* mark  = (const float*)d_in[2];
    const float* W_s   = (const float*)d_in[3];
    const float* b_s   = (const float*)d_in[4];
    const float* W_ld  = (const float*)d_in[5];
    const float* b_ld  = (const float*)d_in[6];
    const float* W_d   = (const float*)d_in[7];
    const float* b_d   = (const float*)d_in[8];
    const float* W_ih  = (const float*)d_in[9];
    const float* b_ih  = (const float*)d_in[10];
    const float* W_hh  = (const float*)d_in[11];
    const float* b_hh  = (const float*)d_in[12];
    const float* W_pd  = (const float*)d_in[13];
    const float* b_pd  = (const float*)d_in[14];
    const float* W_pld = (const float*)d_in[15];
    const float* b_pld = (const float*)d_in[16];
    const float* W_pq  = (const float*)d_in[17];
    const float* b_pq  = (const float*)d_in[18];
    const float* W_pr  = (const float*)d_in[19];
    const float* b_pr  = (const float*)d_in[20];
    const float* attn_W= (const float*)d_in[21];
    float* out = (float*)d_out;

    cudaFuncSetAttribute(drl_main, cudaFuncAttributeMaxDynamicSharedMemorySize,
                         (int)sizeof(SmemLayout));

    precompute_kernel<<<84, 512>>>(W_s, b_s, W_ld, b_ld, W_d, b_d,
                                   W_ih, b_ih, W_hh, b_hh,
                                   W_pd, b_pd, W_pld, b_pld,
                                   W_pq, b_pq, W_pr, b_pr, attn_W);

    precompute_base<<<BTOT, 256>>>(stat, dyn);

    drl_main<<<NBLK, NTHR, sizeof(SmemLayout)>>>(stat, dyn, mark, out);
}

// round 17
// speedup vs baseline: 1.9936x; 1.0180x over previous
#include <cuda_runtime.h>
#include <math.h>

#define H    128
#define SEQ  128
#define BTOT 2048
#define NB   8             // batches per block
#define NBLK (BTOT/NB)     // 256 blocks
#define NTHR 512
#define O5   640           // 512 (W_hh cols) + 128 (W_pq cols), transposed layout

typedef unsigned long long ull;
typedef unsigned int uint32;

// ---------------- device-global scratch -------------------------------------
__device__ float  d_Wt[H*O5];
__device__ float4 d_A4[H];
__device__ float  d_cbias[H];
__device__ float  d_aW[H];
__device__ float  d_G2[512*2];
__device__ float  d_gb[512];
__device__ float  d_base[(size_t)BTOT*H*SEQ];   // 128 MiB: t-invariant attention pre-activation

// ---------------- f32x2 packed helpers --------------------------------------
__device__ __forceinline__ ull pack2(float x, float y) {
    ull r; asm("mov.b64 %0, {%1,%2};" : "=l"(r) : "f"(x), "f"(y)); return r;
}
__device__ __forceinline__ ull fma2(ull a, ull b, ull c) {
    ull d; asm("fma.rn.f32x2 %0, %1, %2, %3;" : "=l"(d) : "l"(a), "l"(b), "l"(c)); return d;
}
__device__ __forceinline__ void unpack2(ull p, float& x, float& y) {
    asm("mov.b64 {%0,%1}, %2;" : "=f"(x), "=f"(y) : "l"(p));
}
// cheap HW tanh (MUFU.TANH f32) — R11-proven; do NOT add instructions here
__device__ __forceinline__ float tanh_fast(float x) {
    float y;
    asm("tanh.approx.f32 %0, %1;" : "=f"(y) : "f"(x));
    return y;
}

// ---------------- exact transcendentals (R4-bitwise) ------------------------
__device__ __forceinline__ float exp_acc(float y) {
    const float L2E_HI = 1.44269502162933349609375f;
    const float L2E_LO = 1.9259629911266175e-8f;
    float p  = y * L2E_HI;
    float e  = fmaf(y, L2E_HI, -p);
    float pc = fminf(fmaxf(p, -126.0f), 126.0f);
    float nf = rintf(pc);
    int   ni = (int)nf;
    float f  = (pc - nf) + fmaf(y, L2E_LO, e);
    float r  = 1.5252733e-5f;
    r = fmaf(r, f, 1.5403530e-4f);
    r = fmaf(r, f, 1.3333558e-3f);
    r = fmaf(r, f, 9.6181291e-3f);
    r = fmaf(r, f, 5.5504109e-2f);
    r = fmaf(r, f, 2.4022651e-1f);
    r = fmaf(r, f, 6.9314718e-1f);
    r = fmaf(r, f, 1.0f);
    float sc = __int_as_float((ni + 127) << 23);
    return r * sc;
}
__device__ __forceinline__ float rcp_nr(float d) {
    float r;
    asm("rcp.approx.f32 %0, %1;" : "=f"(r) : "f"(d));
    return r * fmaf(-d, r, 2.0f);
}
__device__ __forceinline__ float tanh_acc(float x) {
    float E = exp_acc(x + x);
    float q = rcp_nr(E + 1.0f);
    return 1.0f - (q + q);
}
__device__ __forceinline__ float sig_acc(float x) {
    return rcp_nr(1.0f + exp_acc(-x));
}

// ---------------- phase 0: fold affine algebra (fp64) — UNCHANGED -----------
__global__ void precompute_kernel(
    const float* __restrict__ W_s,  const float* __restrict__ b_s,
    const float* __restrict__ W_ld, const float* __restrict__ b_ld,
    const float* __restrict__ W_d,  const float* __restrict__ b_d,
    const float* __restrict__ W_ih, const float* __restrict__ b_ih,
    const float* __restrict__ W_hh, const float* __restrict__ b_hh,
    const float* __restrict__ W_pd, const float* __restrict__ b_pd,
    const float* __restrict__ W_pld,const float* __restrict__ b_pld,
    const float* __restrict__ W_pq, const float* __restrict__ b_pq,
    const float* __restrict__ W_pr, const float* __restrict__ b_pr,
    const float* __restrict__ attn_W)
{
    int tid  = blockIdx.x * blockDim.x + threadIdx.x;
    int nthr = gridDim.x * blockDim.x;

    for (int idx = tid; idx < H*O5; idx += nthr) {
        int k = idx / O5, o = idx % O5;
        d_Wt[idx] = (o < 512) ? W_hh[o*H + k] : W_pq[(o-512)*H + k];
    }
    for (int h = tid; h < H; h += nthr) {
        double ms0=0, ms1=0, wld=0, wd=0, bb=0;
        for (int k = 0; k < H; k++) {
            double wpr  = (double)W_pr [h*H+k];
            double wpld = (double)W_pld[h*H+k];
            double wpd  = (double)W_pd [h*H+k];
            ms0 += wpr  * (double)W_s[k*2+0];
            ms1 += wpr  * (double)W_s[k*2+1];
            wld += wpld * ((double)W_ld[k*2+0] + (double)W_ld[k*2+1]);
            wd  += wpd  * ((double)W_d [k*2+0] + (double)W_d [k*2+1]);
            bb  += wpr*(double)b_s[k] + wpld*(double)b_ld[k] + wpd*(double)b_d[k];
        }
        bb += (double)b_pr[h] + (double)b_pld[h] + (double)b_pd[h] + (double)b_pq[h];
        d_A4[h]    = make_float4((float)ms0, (float)ms1, (float)wld, (float)wd);
        d_cbias[h] = (float)bb;
        d_aW[h]    = attn_W[h];
    }
    for (int o = tid; o < 512; o += nthr) {
        double g0=0, g1=0, gb=0;
        for (int k = 0; k < H; k++) {
            double w = (double)W_ih[o*H+k];
            g0 += w * (double)W_s[k*2+0];
            g1 += w * (double)W_s[k*2+1];
            gb += w * (double)b_s[k];
        }
        d_G2[o*2+0] = (float)g0; d_G2[o*2+1] = (float)g1;
        d_gb[o]     = (float)(gb + (double)b_ih[o] + (double)b_hh[o]);
    }
}

// ---------------- phase 0b: t-invariant attention pre-activation (f32) ------
__global__ void precompute_base(const float* __restrict__ stat,
                                const float* __restrict__ dyn)
{
    const int b   = blockIdx.x;
    const int tid = threadIdx.x;
    __shared__ float4 us[SEQ];
    __shared__ float4 a4s[H];
    for (int s = tid; s < SEQ; s += 256) {
        int g = b * (2*SEQ);
        float s0 = stat[g + s];
        float s1 = stat[g + SEQ + s];
        float ld = dyn [g + s];
        float dm = dyn [g + SEQ + s];
        us[s] = make_float4(s0, s1, ld - dm, dm);
    }
    for (int i = tid; i < H; i += 256) a4s[i] = d_A4[i];
    __syncthreads();
    float* bp = d_base + (size_t)b * H * SEQ;
    for (int idx = tid; idx < H*SEQ; idx += 256) {
        int s = idx & 127, hh = idx >> 7;
        float4 a = a4s[hh];
        float4 u = us[s];
        bp[idx] = fmaf(a.x,u.x, fmaf(a.y,u.y, fmaf(a.z,u.z, a.w*u.w)));
    }
}

// ---------------- main kernel ------------------------------------------------
struct SmemLayout {
    float4 u[NB][SEQ];       // 16KB (exact pass + v update)
    float4 A4[H];            //  2KB (exact pass)
    float  ht[H*8];          //  4KB  ht[k*8+b]
    float  ct[H*8];          //  4KB
    float2 qa[NB][H];        //  8KB  {q + cbias, aW}
    float  gt[512*9];        // 18KB  gt[o*9+b]
    float  G2[512][2];       //  4KB
    float  gb[512];          //  2KB
    float  cbias[H];
    float  aW[H];
    float2 v[NB];
    float  red_m [NB][2];
    int    red_mi[NB][2];
    float  red_ds[NB][2];
};

extern __shared__ char smem_raw[];

__global__ void __launch_bounds__(NTHR, 2)
drl_main(const float* __restrict__ stat, const float* __restrict__ dyn,
         const float* __restrict__ mark, float* __restrict__ out)
{
    SmemLayout& sm = *reinterpret_cast<SmemLayout*>(smem_raw);
    const int tid = threadIdx.x;
    const int b0  = blockIdx.x * NB;

    for (int i = tid; i < H; i += NTHR) {
        sm.A4[i]    = d_A4[i];
        sm.cbias[i] = d_cbias[i];
        sm.aW[i]    = d_aW[i];
    }
    for (int i = tid; i < 512; i += NTHR) {
        sm.G2[i][0] = d_G2[i*2+0];
        sm.G2[i][1] = d_G2[i*2+1];
        sm.gb[i]    = d_gb[i];
    }
    for (int idx = tid; idx < NB*SEQ; idx += NTHR) {
        int b = idx >> 7, s = idx & 127;
        int g = (b0 + b) * (2*SEQ);
        float s0 = stat[g + s];
        float s1 = stat[g + SEQ + s];
        float ld = dyn [g + s];
        float dm = dyn [g + SEQ + s];
        sm.u[b][s] = make_float4(s0, s1, ld - dm, dm);
    }
    for (int idx = tid; idx < H*8; idx += NTHR) {
        sm.ht[idx] = 0.f;
        sm.ct[idx] = 0.f;
    }
    __syncthreads();
    if (tid < NB) sm.v[tid] = make_float2(sm.u[tid][0].x, sm.u[tid][0].y);
    if (blockIdx.x == 0 && tid == 0) out[2*BTOT*SEQ] = mark[0];
    __syncthreads();

    const int o4   = (tid & 127) * 4;   // GEMM1: 4 consecutive outputs
    const int g1bg = tid >> 7;          // GEMM1: batch-pair group (0..3)
    const int o2   = tid & 127;         // GEMM2 output column
    const int bg   = tid >> 7;          // GEMM2 batch group (2 batches each)
    const int warp = tid >> 5;
    const int lane = tid & 31;
    const int ab   = warp >> 1;    // attention batch
    const int ah   = warp & 1;     // attention s-half
    const float NEG_INF = __int_as_float(0xff800000);
    const float MARGIN  = 0.012f;  // cheap-tanh worst-case bias + tie cell

    for (int t = 0; t < SEQ; t++) {
        // ---- GEMM1: 4 outputs x 2 batches per thread (per-acc chain R4-bitwise) ----
        {
            // init: acc[j] packs batches (2*g1bg, 2*g1bg+1) for output o4+j
            ull acc[4];
            float2 v0 = sm.v[g1bg*2];
            float2 v1 = sm.v[g1bg*2 + 1];
            #pragma unroll
            for (int j = 0; j < 4; j++) {
                int oo = o4 + j;
                float g0 = sm.G2[oo][0], g1v = sm.G2[oo][1], gbv = sm.gb[oo];
                float ax = fmaf(g0, v0.x, fmaf(g1v, v0.y, gbv));
                float ay = fmaf(g0, v1.x, fmaf(g1v, v1.y, gbv));
                acc[j] = pack2(ax, ay);
            }
            #pragma unroll 4
            for (int k = 0; k < H; k++) {
                float4 w4 = *reinterpret_cast<const float4*>(&d_Wt[k*O5 + o4]);
                ull hp = *reinterpret_cast<const ull*>(&sm.ht[k*8 + g1bg*2]);
                acc[0] = fma2(pack2(w4.x, w4.x), hp, acc[0]);
                acc[1] = fma2(pack2(w4.y, w4.y), hp, acc[1]);
                acc[2] = fma2(pack2(w4.z, w4.z), hp, acc[2]);
                acc[3] = fma2(pack2(w4.w, w4.w), hp, acc[3]);
            }
            #pragma unroll
            for (int j = 0; j < 4; j++) {
                float x, y;
                unpack2(acc[j], x, y);
                sm.gt[(o4 + j)*9 + g1bg*2    ] = x;
                sm.gt[(o4 + j)*9 + g1bg*2 + 1] = y;
            }
        }
        __syncthreads();

        // ---- LSTM pointwise (R4-bitwise math) ----
        #pragma unroll
        for (int r = 0; r < (NB*H)/NTHR; r++) {
            int idx = tid + r*NTHR;
            int b = idx & 7, j = idx >> 3;
            float gi = sm.gt[(j      )*9 + b];
            float gf = sm.gt[(j + 128)*9 + b];
            float gg = sm.gt[(j + 256)*9 + b];
            float go = sm.gt[(j + 384)*9 + b];
            float c2 = sig_acc(gf) * sm.ct[j*8+b] + sig_acc(gi) * tanh_acc(gg);
            float h2 = sig_acc(go) * tanh_acc(c2);
            sm.ct[j*8+b] = c2;
            sm.ht[j*8+b] = h2;
        }
        __syncthreads();

        // ---- GEMM2 (f32x2 packed; per-batch chain R4-bitwise) ----
        {
            float cb = sm.cbias[o2];
            ull acc2 = pack2(cb, cb);
            const float* wt = d_Wt + 512 + o2;
            #pragma unroll 4
            for (int k = 0; k < H; k += 4) {
                float w0 = wt[(k+0)*O5];
                float w1 = wt[(k+1)*O5];
                float w2 = wt[(k+2)*O5];
                float w3 = wt[(k+3)*O5];
                ull h0 = *reinterpret_cast<const ull*>(&sm.ht[(k+0)*8 + bg*2]);
                ull h1 = *reinterpret_cast<const ull*>(&sm.ht[(k+1)*8 + bg*2]);
                ull h2 = *reinterpret_cast<const ull*>(&sm.ht[(k+2)*8 + bg*2]);
                ull h3 = *reinterpret_cast<const ull*>(&sm.ht[(k+3)*8 + bg*2]);
                acc2 = fma2(pack2(w0,w0), h0, acc2);
                acc2 = fma2(pack2(w1,w1), h1, acc2);
                acc2 = fma2(pack2(w2,w2), h2, acc2);
                acc2 = fma2(pack2(w3,w3), h3, acc2);
            }
            float qx, qy;
            unpack2(acc2, qx, qy);
            float aw = sm.aW[o2];
            sm.qa[bg*2    ][o2] = make_float2(qx, aw);
            sm.qa[bg*2 + 1][o2] = make_float2(qy, aw);
        }
        __syncthreads();

        // ---- attention: cheap pass (R11-exact loop) + exact candidates ----
        {
            const int b     = ab;
            const int sbase = ah*64 + lane*2;
            const float* bp = d_base + ((size_t)(b0 + b) * H) * SEQ + sbase;
            float c0 = 0.f, c1 = 0.f;
            #pragma unroll 8
            for (int hh = 0; hh < H; hh++) {
                float2 bs = *reinterpret_cast<const float2*>(bp + hh*SEQ);
                float2 qa = sm.qa[b][hh];
                c0 = fmaf(qa.y, tanh_fast(bs.x + qa.x), c0);
                c1 = fmaf(qa.y, tanh_fast(bs.y + qa.x), c1);
            }
            if (ah == 0 && lane == 0) c0 = NEG_INF;   // masked s=0

            float cm = fmaxf(c0, c1);
            #pragma unroll
            for (int off = 16; off; off >>= 1)
                cm = fmaxf(cm, __shfl_xor_sync(0xffffffffu, cm, off));

            unsigned bal0 = __ballot_sync(0xffffffffu, c0 >= cm - MARGIN);
            unsigned bal1 = __ballot_sync(0xffffffffu, c1 >= cm - MARGIN);

            // exact recompute (R4-bitwise z chain, fp64 warp tree)
            #pragma unroll
            for (int j = 0; j < 2; j++) {
                unsigned msk = j ? bal1 : bal0;
                while (msk) {
                    int sl = __ffs(msk) - 1;
                    msk &= msk - 1;
                    int s = ah*64 + sl*2 + j;
                    float4 us = sm.u[b][s];
                    double p = 0.0;
                    #pragma unroll
                    for (int r = 0; r < 4; r++) {
                        int hh = lane + r*32;
                        float4 a  = sm.A4[hh];
                        float2 qa = sm.qa[b][hh];
                        float z = fmaf(a.x,us.x, fmaf(a.y,us.y, fmaf(a.z,us.z, fmaf(a.w,us.w, qa.x))));
                        p += (double)(qa.y * tanh_acc(z));
                    }
                    #pragma unroll
                    for (int off = 16; off; off >>= 1)
                        p += __shfl_xor_sync(0xffffffffu, p, off);
                    if (lane == sl) { if (j) c1 = (float)p; else c0 = (float)p; }
                }
            }

            float aq0 = c0 + 10000.0f;
            float aq1 = c1 + 10000.0f;

            float m  = aq0;
            int   mi = sbase;
            if (aq1 > m) { m = aq1; mi = sbase + 1; }
            #pragma unroll
            for (int off = 16; off; off >>= 1) {
                float om = __shfl_xor_sync(0xffffffffu, m,  off);
                int   oi = __shfl_xor_sync(0xffffffffu, mi, off);
                if (om > m || (om == m && oi < mi)) { m = om; mi = oi; }
            }
            float d0 = aq0 - m, d1 = aq1 - m;
            float dsum = ((d0 == NEG_INF) ? 0.f : exp_acc(d0))
                       + ((d1 == NEG_INF) ? 0.f : exp_acc(d1));
            #pragma unroll
            for (int off = 16; off; off >>= 1)
                dsum += __shfl_xor_sync(0xffffffffu, dsum, off);

            if (lane == 0) {
                sm.red_m [b][ah] = m;
                sm.red_mi[b][ah] = mi;
                sm.red_ds[b][ah] = dsum;
            }

            // pair-scoped barrier: only the 2 warps of this batch sync,
            // then the half-0 leader combines (same arithmetic as before).
            asm volatile("bar.sync %0, 64;" :: "r"(1 + ab) : "memory");
            if (ah == 0 && lane == 0) {
                float m0 = sm.red_m[b][0], m1 = sm.red_m[b][1];
                int  mi0 = sm.red_mi[b][0], mi1 = sm.red_mi[b][1];
                float dd0 = sm.red_ds[b][0], dd1 = sm.red_ds[b][1];
                float mm; int mmi;
                if (m1 > m0 || (m1 == m0 && mi1 < mi0)) { mm = m1; mmi = mi1; }
                else                                    { mm = m0; mmi = mi0; }
                float dsumc = dd0 * exp_acc(m0 - mm) + dd1 * exp_acc(m1 - mm);
                out[(b0 + b)*SEQ + t]            = (float)mmi;
                out[BTOT*SEQ + (b0 + b)*SEQ + t] = -logf(dsumc);
                sm.v[b] = make_float2(sm.u[b][mmi].x, sm.u[b][mmi].y);
            }
        }
        __syncthreads();
    }
}

// ---------------- launch --------------------------------------------------
extern "C" void kernel_launch(void* const* d_in, const int* in_sizes, int n_in,
                              void* d_out, int out_size)
{
    (void)in_sizes; (void)n_in; (void)out_size;
    const float* stat  = (const float*)d_in[0];
    const float* dyn   = (const float*)d_in[1];
    const float* mark  = (const float*)d_in[2];
    const float* W_s   = (const float*)d_in[3];
    const float* b_s   = (const float*)d_in[4];
    const float* W_ld  = (const float*)d_in[5];
    const float* b_ld  = (const float*)d_in[6];
    const float* W_d   = (const float*)d_in[7];
    const float* b_d   = (const float*)d_in[8];
    const float* W_ih  = (const float*)d_in[9];
    const float* b_ih  = (const float*)d_in[10];
    const float* W_hh  = (const float*)d_in[11];
    const float* b_hh  = (const float*)d_in[12];
    const float* W_pd  = (const float*)d_in[13];
    const float* b_pd  = (const float*)d_in[14];
    const float* W_pld = (const float*)d_in[15];
    const float* b_pld = (const float*)d_in[16];
    const float* W_pq  = (const float*)d_in[17];
    const float* b_pq  = (const float*)d_in[18];
    const float* W_pr  = (const float*)d_in[19];
    const float* b_pr  = (const float*)d_in[20];
    const float* attn_W= (const float*)d_in[21];
    float* out = (float*)d_out;

    cudaFuncSetAttribute(drl_main, cudaFuncAttributeMaxDynamicSharedMemorySize,
                         (int)sizeof(SmemLayout));

    precompute_kernel<<<84, 512>>>(W_s, b_s, W_ld, b_ld, W_d, b_d,
                                   W_ih, b_ih, W_hh, b_hh,
                                   W_pd, b_pd, W_pld, b_pld,
                                   W_pq, b_pq, W_pr, b_pr, attn_W);

    precompute_base<<<BTOT, 256>>>(stat, dyn);

    drl_main<<<NBLK, NTHR, sizeof(SmemLayout)>>>(stat, dyn, mark, out);
}